// round 2
// baseline (speedup 1.0000x reference)
#include <cuda_runtime.h>
#include <math_constants.h>

#define NTOK 1024
#define DIM 128
#define TI 8            // rows per block (kernel 2)
#define TJ 64           // j-tile
#define NT2 512         // threads, kernel 2
#define PITCH 129       // smem tile pitch (conflict-free both ways)
#define NTILE (NTOK / TJ)
#define LOG2E 1.4426950408889634f

// scratch for Q,K,V (static device arrays — no allocation)
__device__ float g_Q[NTOK * DIM];
__device__ float g_K[NTOK * DIM];
__device__ float g_V[NTOK * DIM];

// ---------------------------------------------------------------------------
// Kernel 1: Q,K,V = x @ W + b.  128 blocks x 384 threads, 8 rows per block,
// thread (d, mat) computes 8 output elements of one matrix.
// ---------------------------------------------------------------------------
__global__ __launch_bounds__(384) void qkv_kernel(
    const float* __restrict__ x,
    const float* __restrict__ WQ, const float* __restrict__ bQ,
    const float* __restrict__ WK, const float* __restrict__ bK,
    const float* __restrict__ WV, const float* __restrict__ bV)
{
    __shared__ float xs[8 * DIM];
    const int tid = threadIdx.x;
    const int i0 = blockIdx.x * 8;

    for (int idx = tid; idx < 8 * DIM; idx += 384)
        xs[idx] = x[i0 * DIM + idx];
    __syncthreads();

    const int d   = tid & 127;
    const int mat = tid >> 7;   // 0=Q 1=K 2=V
    const float* W = (mat == 0) ? WQ : (mat == 1) ? WK : WV;
    const float* b = (mat == 0) ? bQ : (mat == 1) ? bK : bV;
    float* outp    = (mat == 0) ? g_Q : (mat == 1) ? g_K : g_V;

    float acc[8];
    const float bv = b[d];
#pragma unroll
    for (int r = 0; r < 8; r++) acc[r] = bv;

    for (int k = 0; k < DIM; k += 4) {
        const float w0 = W[(k + 0) * DIM + d];
        const float w1 = W[(k + 1) * DIM + d];
        const float w2 = W[(k + 2) * DIM + d];
        const float w3 = W[(k + 3) * DIM + d];
#pragma unroll
        for (int r = 0; r < 8; r++) {
            const float4 xq = *(const float4*)&xs[r * DIM + k];
            acc[r] = fmaf(xq.x, w0, fmaf(xq.y, w1, fmaf(xq.z, w2, fmaf(xq.w, w3, acc[r]))));
        }
    }
#pragma unroll
    for (int r = 0; r < 8; r++)
        outp[(i0 + r) * DIM + d] = acc[r];
}

// ---------------------------------------------------------------------------
// Kernel 2: fused flash-style pass, 512 threads (16 warps = 4/SMSP).
//   per row i: online softmax over j of e_ij = relu(Q_i+K_j).wA
//   accumulate R_i = sum_j p_ij relu(Q_i+K_j),  AV_i = sum_j p_ij V_j
//   epilogue:  out_i = AV_i/l + (R_i/l) @ W_Ev + b_Ev
// 128 blocks (8 rows each). Dynamic smem ~78.4 KB (1 CTA/SM by design).
// ---------------------------------------------------------------------------
__global__ __launch_bounds__(NT2) void attn_kernel(
    const float* __restrict__ wA,
    const float* __restrict__ W_Ev,
    const float* __restrict__ b_Ev,
    float* __restrict__ out)
{
    extern __shared__ float sm[];
    // layout (floats):
    float2* Qf2    = (float2*)sm;        // [DIM*8] float2 = 2048 floats: {Q[i0+r][d], wA[d]}
    float*  Ks     = sm + 2048;          // [TJ][PITCH] = 8256
    float*  Vs     = sm + 2048 + 8256;   // 8256
    float*  e_s    = sm + 18560;         // [8][TJ] = 512
    float*  p2s    = sm + 19072;         // [TJ][8] = 512
    float*  scale_s= sm + 19584;         // [8]
    float*  l_s    = sm + 19592;         // [8]
    // total 19600 floats = 78400 B

    const int tid  = threadIdx.x;
    const int lane = tid & 31;
    const int warp = tid >> 5;           // softmax: warp w (w<8) owns row w
    const int je   = tid & 63;           // phase-e: j within tile
    const int re   = tid >> 6;           // phase-e: row 0..7
    const int d    = tid & 127;          // accum: feature dim
    const int h    = tid >> 7;           // accum: row group (rows 2h, 2h+1)
    const int i0   = blockIdx.x * TI;

    // packed Q/wA broadcast table: Qf2[dd*8 + r] = {Q[i0+r][dd], wA[dd]}
    for (int idx = tid; idx < DIM * 8; idx += NT2) {
        const int dd = idx >> 3, rr = idx & 7;
        Qf2[idx] = make_float2(g_Q[(i0 + rr) * DIM + dd], wA[dd]);
    }

    // accum-phase Q rows live in registers (rows 2h, 2h+1 at dim d)
    const float q0 = g_Q[(i0 + 2 * h + 0) * DIM + d];
    const float q1 = g_Q[(i0 + 2 * h + 1) * DIM + d];

    float af0 = 0.f, af1 = 0.f;   // relu-feature accum
    float av0 = 0.f, av1 = 0.f;   // V accum
    float m_w = -1e30f, l_w = 0.f;

    for (int ti = 0; ti < NTILE; ti++) {
        const float* Kgt = g_K + ti * TJ * DIM;
        const float* Vgt = g_V + ti * TJ * DIM;
        __syncthreads();   // previous accum done (also covers Qf2 on first iter)
        for (int idx = tid; idx < TJ * DIM; idx += NT2) {
            const int j = idx >> 7, c = idx & 127;
            Ks[j * PITCH + c] = Kgt[idx];
            Vs[j * PITCH + c] = Vgt[idx];
        }
        __syncthreads();

        // ---- phase e: each thread computes e for (re, je)
        {
            float e0 = 0.f;
            const float* kp = Ks + je * PITCH;
#pragma unroll 8
            for (int dd = 0; dd < DIM; dd++) {
                const float2 qw = Qf2[dd * 8 + re];   // 8B broadcast (r const in warp)
                e0 += fmaxf(qw.x + kp[dd], 0.f) * qw.y;
            }
            e_s[re * TJ + je] = e0;
        }
        __syncthreads();

        // ---- online softmax: warp w<8 reduces row w (64 values)
        if (warp < 8) {
            const float v1 = e_s[warp * TJ + lane];
            const float v2 = e_s[warp * TJ + 32 + lane];
            float mx = fmaxf(v1, v2);
#pragma unroll
            for (int off = 16; off; off >>= 1)
                mx = fmaxf(mx, __shfl_xor_sync(0xffffffffu, mx, off));
            const float m_new = fmaxf(m_w, mx);
            const float p1 = exp2f((v1 - m_new) * LOG2E);
            const float p2 = exp2f((v2 - m_new) * LOG2E);
            p2s[lane * 8 + warp]        = p1;
            p2s[(lane + 32) * 8 + warp] = p2;
            float s = p1 + p2;
#pragma unroll
            for (int off = 16; off; off >>= 1)
                s += __shfl_xor_sync(0xffffffffu, s, off);
            const float sc = exp2f((m_w - m_new) * LOG2E);
            l_w = l_w * sc + s;
            m_w = m_new;
            if (lane == 0) scale_s[warp] = sc;
        }
        __syncthreads();

        // ---- accumulate: thread owns dim d, rows 2h, 2h+1
        const float2 sc2 = *(const float2*)&scale_s[2 * h];
        af0 *= sc2.x; av0 *= sc2.x;
        af1 *= sc2.y; av1 *= sc2.y;
#pragma unroll 4
        for (int j = 0; j < TJ; j++) {
            const float kv = Ks[j * PITCH + d];
            const float vv = Vs[j * PITCH + d];
            const float2 p = *(const float2*)&p2s[j * 8 + 2 * h];  // 8B broadcast
            af0 += p.x * fmaxf(q0 + kv, 0.f); av0 += p.x * vv;
            af1 += p.y * fmaxf(q1 + kv, 0.f); av1 += p.y * vv;
        }
    }

    // publish softmax denominators
    if (warp < 8 && lane == 0) l_s[warp] = l_w;
    __syncthreads();   // also: everyone done reading Ks (reused as Rp below)
    const float2 l2 = *(const float2*)&l_s[2 * h];
    const float il0 = 1.f / l2.x, il1 = 1.f / l2.y;

    // stash R (normalized relu-feature accum) packed as Rp[k][8], reuse Ks
    float* Rp = Ks;
    Rp[d * 8 + 2 * h + 0] = af0 * il0;
    Rp[d * 8 + 2 * h + 1] = af1 * il1;
    __syncthreads();

    // epilogue: out = AV/l + R @ W_Ev + b_Ev
    const float bv = b_Ev[d];
    float o0 = av0 * il0 + bv;
    float o1 = av1 * il1 + bv;
#pragma unroll 4
    for (int k = 0; k < DIM; k++) {
        const float wv = W_Ev[k * DIM + d];
        const float2 r2 = *(const float2*)&Rp[k * 8 + 2 * h];
        o0 += r2.x * wv; o1 += r2.y * wv;
    }
    out[(i0 + 2 * h + 0) * DIM + d] = o0;
    out[(i0 + 2 * h + 1) * DIM + d] = o1;
}

// ---------------------------------------------------------------------------
extern "C" void kernel_launch(void* const* d_in, const int* in_sizes, int n_in,
                              void* d_out, int out_size)
{
    const float* x    = (const float*)d_in[0];
    const float* W_Q  = (const float*)d_in[1];
    const float* b_Q  = (const float*)d_in[2];
    const float* W_K  = (const float*)d_in[3];
    const float* b_K  = (const float*)d_in[4];
    const float* W_V  = (const float*)d_in[5];
    const float* b_V  = (const float*)d_in[6];
    const float* W_Ev = (const float*)d_in[7];
    const float* b_Ev = (const float*)d_in[8];
    const float* W_A  = (const float*)d_in[9];
    // d_in[10] = b_A: cancels in softmax, and sum(alpha)=1 handles b_Ev; unused.
    float* out = (float*)d_out;

    const int smem2 = 19600 * (int)sizeof(float);  // 78400 B
    cudaFuncSetAttribute(attn_kernel, cudaFuncAttributeMaxDynamicSharedMemorySize, smem2);

    qkv_kernel<<<NTOK / 8, 384>>>(x, W_Q, b_Q, W_K, b_K, W_V, b_V);
    attn_kernel<<<NTOK / TI, NT2, smem2>>>(W_A, W_Ev, b_Ev, out);
}

// round 5
// speedup vs baseline: 1.5024x; 1.5024x over previous
#include <cuda_runtime.h>
#include <math_constants.h>

#define NTOK 1024
#define DIM 128
#define TI 4            // rows per block (attn)
#define TJ 64           // j-tile
#define NT 256          // threads, attn
#define KP 132          // K/V smem pitch (float4-aligned, conflict-free for our patterns)
#define NTILE (NTOK / TJ)
#define LOG2E 1.4426950408889634f

// scratch for Q,K,V (static device arrays — no allocation)
__device__ float g_Q[NTOK * DIM];
__device__ float g_K[NTOK * DIM];
__device__ float g_V[NTOK * DIM];

// ---------------------------------------------------------------------------
// Kernel 1: Q,K,V = x @ W + b.  128 blocks x 384 threads.
// ---------------------------------------------------------------------------
__global__ __launch_bounds__(384) void qkv_kernel(
    const float* __restrict__ x,
    const float* __restrict__ WQ, const float* __restrict__ bQ,
    const float* __restrict__ WK, const float* __restrict__ bK,
    const float* __restrict__ WV, const float* __restrict__ bV)
{
    __shared__ float xs[8 * DIM];
    const int tid = threadIdx.x;
    const int i0 = blockIdx.x * 8;

    for (int idx = tid; idx < 8 * DIM; idx += 384)
        xs[idx] = x[i0 * DIM + idx];
    __syncthreads();

    const int d   = tid & 127;
    const int mat = tid >> 7;   // 0=Q 1=K 2=V
    const float* W = (mat == 0) ? WQ : (mat == 1) ? WK : WV;
    const float* b = (mat == 0) ? bQ : (mat == 1) ? bK : bV;
    float* outp    = (mat == 0) ? g_Q : (mat == 1) ? g_K : g_V;

    float acc[8];
    const float bv = b[d];
#pragma unroll
    for (int r = 0; r < 8; r++) acc[r] = bv;

    for (int k = 0; k < DIM; k += 4) {
        const float w0 = W[(k + 0) * DIM + d];
        const float w1 = W[(k + 1) * DIM + d];
        const float w2 = W[(k + 2) * DIM + d];
        const float w3 = W[(k + 3) * DIM + d];
#pragma unroll
        for (int r = 0; r < 8; r++) {
            const float4 xq = *(const float4*)&xs[r * DIM + k];
            acc[r] = fmaf(xq.x, w0, fmaf(xq.y, w1, fmaf(xq.z, w2, fmaf(xq.w, w3, acc[r]))));
        }
    }
#pragma unroll
    for (int r = 0; r < 8; r++)
        outp[(i0 + r) * DIM + d] = acc[r];
}

// ---------------------------------------------------------------------------
// Kernel 2: fused flash-style pass. TI=4 rows/block, 256 blocks, 256 threads,
// smem 72.3KB -> 2 CTAs/SM.
// phase-e: thread (je, g) computes e[4 rows] partial over 1/4 of d (K via
//          LDS.128, read once per (j,d)); shfl-reduce over g.
// softmax: warp r (r<4) owns row r, online max/sum, writes packed p8[j][4].
// accumulate: thread (d, jc) owns all 4 rows, half the j's; K/V read once.
// epilogue: combine jc-partials, R@W_Ev split over jc, combine, store.
// ---------------------------------------------------------------------------
__global__ __launch_bounds__(NT, 2) void attn_kernel(
    const float* __restrict__ wA,
    const float* __restrict__ W_Ev,
    const float* __restrict__ b_Ev,
    float* __restrict__ out)
{
    extern __shared__ float sm[];
    float* Ks      = sm;             // [TJ][KP] = 8448
    float* Vs      = sm + 8448;      // 8448
    float* Qe      = sm + 16896;     // [DIM][4]: Qe[dd*4+r] = Q[i0+r][dd]
    float* wAs     = sm + 17408;     // [DIM]
    float* e_s     = sm + 17536;     // [4][64]
    float* p8      = sm + 17792;     // [TJ][4] packed softmax weights
    float* scale_s = sm + 18048;     // [4]
    float* l_s     = sm + 18052;     // [4]
    // total 18056 floats (72.3 KB incl. pad)

    const int tid  = threadIdx.x;
    const int lane = tid & 31;
    const int warp = tid >> 5;
    const int i0   = blockIdx.x * TI;
    // phase-e ids: je in [0,64), g = d-chunk in [0,4)
    const int je   = warp * 8 + (lane & 7);
    const int g    = lane >> 3;
    // accumulate ids
    const int d    = tid & 127;
    const int jc   = tid >> 7;       // j-half

    // init Q table + wA
    for (int idx = tid; idx < TI * DIM; idx += NT) {
        const int r = idx & 3, dd = idx >> 2;
        Qe[dd * 4 + r] = g_Q[(i0 + r) * DIM + dd];
    }
    if (tid < DIM) wAs[tid] = wA[tid];

    // accumulate-phase Q rows in registers
    const float q0 = g_Q[(i0 + 0) * DIM + d];
    const float q1 = g_Q[(i0 + 1) * DIM + d];
    const float q2 = g_Q[(i0 + 2) * DIM + d];
    const float q3 = g_Q[(i0 + 3) * DIM + d];

    float af0 = 0.f, af1 = 0.f, af2 = 0.f, af3 = 0.f;
    float av0 = 0.f, av1 = 0.f, av2 = 0.f, av3 = 0.f;
    float m_w = -1e30f, l_w = 0.f;

    for (int ti = 0; ti < NTILE; ti++) {
        const float4* Kg = (const float4*)(g_K + ti * TJ * DIM);
        const float4* Vg = (const float4*)(g_V + ti * TJ * DIM);
        __syncthreads();   // prev accumulate done with Ks/Vs (covers Qe/wAs on ti=0)
        // tile = TJ*DIM/4 = 2048 float4s = 8 iterations of 256 threads
#pragma unroll
        for (int it = 0; it < 8; it++) {
            const int idx = it * NT + tid;        // float4 index in tile
            const int j = idx >> 5, c4 = idx & 31;
            *(float4*)&Ks[j * KP + c4 * 4] = Kg[idx];
            *(float4*)&Vs[j * KP + c4 * 4] = Vg[idx];
        }
        __syncthreads();

        // ---- phase e: partial e over d-chunk g for 4 rows at column je
        {
            float e0 = 0.f, e1 = 0.f, e2 = 0.f, e3 = 0.f;
            const float* kp = Ks + je * KP;
#pragma unroll
            for (int it = 0; it < 8; it++) {
                const int b = g + it * 4;                       // float4 block id
                const float4 k4 = *(const float4*)&kp[b * 4];   // conflict-free
                const float4 wa = *(const float4*)&wAs[b * 4];  // broadcast
                {
                    const float4 qa = *(const float4*)&Qe[(4 * b + 0) * 4];
                    e0 += fmaxf(qa.x + k4.x, 0.f) * wa.x;
                    e1 += fmaxf(qa.y + k4.x, 0.f) * wa.x;
                    e2 += fmaxf(qa.z + k4.x, 0.f) * wa.x;
                    e3 += fmaxf(qa.w + k4.x, 0.f) * wa.x;
                }
                {
                    const float4 qa = *(const float4*)&Qe[(4 * b + 1) * 4];
                    e0 += fmaxf(qa.x + k4.y, 0.f) * wa.y;
                    e1 += fmaxf(qa.y + k4.y, 0.f) * wa.y;
                    e2 += fmaxf(qa.z + k4.y, 0.f) * wa.y;
                    e3 += fmaxf(qa.w + k4.y, 0.f) * wa.y;
                }
                {
                    const float4 qa = *(const float4*)&Qe[(4 * b + 2) * 4];
                    e0 += fmaxf(qa.x + k4.z, 0.f) * wa.z;
                    e1 += fmaxf(qa.y + k4.z, 0.f) * wa.z;
                    e2 += fmaxf(qa.z + k4.z, 0.f) * wa.z;
                    e3 += fmaxf(qa.w + k4.z, 0.f) * wa.z;
                }
                {
                    const float4 qa = *(const float4*)&Qe[(4 * b + 3) * 4];
                    e0 += fmaxf(qa.x + k4.w, 0.f) * wa.w;
                    e1 += fmaxf(qa.y + k4.w, 0.f) * wa.w;
                    e2 += fmaxf(qa.z + k4.w, 0.f) * wa.w;
                    e3 += fmaxf(qa.w + k4.w, 0.f) * wa.w;
                }
            }
            // reduce partials across g (lanes l^8, l^16 share je)
#pragma unroll
            for (int off = 8; off <= 16; off <<= 1) {
                e0 += __shfl_xor_sync(0xffffffffu, e0, off);
                e1 += __shfl_xor_sync(0xffffffffu, e1, off);
                e2 += __shfl_xor_sync(0xffffffffu, e2, off);
                e3 += __shfl_xor_sync(0xffffffffu, e3, off);
            }
            if ((lane & 24) == 0) {   // lanes 0..7
                e_s[0 * 64 + je] = e0;
                e_s[1 * 64 + je] = e1;
                e_s[2 * 64 + je] = e2;
                e_s[3 * 64 + je] = e3;
            }
        }
        __syncthreads();

        // ---- online softmax: warp r<4 owns row r
        if (warp < TI) {
            const float v1 = e_s[warp * 64 + lane];
            const float v2 = e_s[warp * 64 + 32 + lane];
            float mx = fmaxf(v1, v2);
#pragma unroll
            for (int off = 16; off; off >>= 1)
                mx = fmaxf(mx, __shfl_xor_sync(0xffffffffu, mx, off));
            const float m_new = fmaxf(m_w, mx);
            const float p1 = exp2f((v1 - m_new) * LOG2E);
            const float p2 = exp2f((v2 - m_new) * LOG2E);
            p8[lane * 4 + warp]        = p1;
            p8[(lane + 32) * 4 + warp] = p2;
            float s = p1 + p2;
#pragma unroll
            for (int off = 16; off; off >>= 1)
                s += __shfl_xor_sync(0xffffffffu, s, off);
            const float sc = exp2f((m_w - m_new) * LOG2E);
            l_w = l_w * sc + s;
            m_w = m_new;
            if (lane == 0) scale_s[warp] = sc;
        }
        __syncthreads();

        // ---- accumulate: thread owns dim d, rows 0..3, j-half jc
        {
            const float4 sc4 = *(const float4*)scale_s;   // broadcast
            af0 *= sc4.x; av0 *= sc4.x;
            af1 *= sc4.y; av1 *= sc4.y;
            af2 *= sc4.z; av2 *= sc4.z;
            af3 *= sc4.w; av3 *= sc4.w;
            const float* kp = Ks + (jc * 32) * KP + d;
            const float* vp = Vs + (jc * 32) * KP + d;
            const float* pp = p8 + jc * 32 * 4;
#pragma unroll 4
            for (int j = 0; j < 32; j++) {
                const float kv = kp[j * KP];
                const float vv = vp[j * KP];
                const float4 p = *(const float4*)&pp[j * 4];  // broadcast
                af0 += p.x * fmaxf(q0 + kv, 0.f); av0 += p.x * vv;
                af1 += p.y * fmaxf(q1 + kv, 0.f); av1 += p.y * vv;
                af2 += p.z * fmaxf(q2 + kv, 0.f); av2 += p.z * vv;
                af3 += p.w * fmaxf(q3 + kv, 0.f); av3 += p.w * vv;
            }
        }
    }

    // ================= epilogue =================
    // publish softmax denominators (THE fix: was missing -> NaN)
    if (warp < TI && lane == 0) l_s[warp] = l_w;
    __syncthreads();                 // l_s published; accumulate reads of Ks/Vs done
    float* xch = Ks;                 // [8][128] exchange buffer
    if (jc == 1) {
        xch[0 * 128 + d] = af0; xch[1 * 128 + d] = af1;
        xch[2 * 128 + d] = af2; xch[3 * 128 + d] = af3;
        xch[4 * 128 + d] = av0; xch[5 * 128 + d] = av1;
        xch[6 * 128 + d] = av2; xch[7 * 128 + d] = av3;
    }
    __syncthreads();

    const float4 l4 = *(const float4*)l_s;
    const float il0 = 1.f / l4.x, il1 = 1.f / l4.y;
    const float il2 = 1.f / l4.z, il3 = 1.f / l4.w;

    float* Rp = Vs;                  // [128][4] normalized R, k-major packed
    if (jc == 0) {
        af0 += xch[0 * 128 + d]; af1 += xch[1 * 128 + d];
        af2 += xch[2 * 128 + d]; af3 += xch[3 * 128 + d];
        av0 += xch[4 * 128 + d]; av1 += xch[5 * 128 + d];
        av2 += xch[6 * 128 + d]; av3 += xch[7 * 128 + d];
        Rp[d * 4 + 0] = af0 * il0;
        Rp[d * 4 + 1] = af1 * il1;
        Rp[d * 4 + 2] = af2 * il2;
        Rp[d * 4 + 3] = af3 * il3;
    }
    __syncthreads();

    // GEMM: o[r][d] partial over k-range of this jc
    float o0 = 0.f, o1 = 0.f, o2 = 0.f, o3 = 0.f;
    {
        const float* Wp = W_Ev + jc * 64 * DIM + d;
#pragma unroll 4
        for (int k = 0; k < 64; k++) {
            const float wv = Wp[k * DIM];
            const float4 r4 = *(const float4*)&Rp[(jc * 64 + k) * 4];  // broadcast
            o0 += r4.x * wv; o1 += r4.y * wv; o2 += r4.z * wv; o3 += r4.w * wv;
        }
    }
    __syncthreads();
    if (jc == 1) {
        xch[0 * 128 + d] = o0; xch[1 * 128 + d] = o1;
        xch[2 * 128 + d] = o2; xch[3 * 128 + d] = o3;
    }
    __syncthreads();
    if (jc == 0) {
        const float bv = b_Ev[d];
        o0 += xch[0 * 128 + d] + av0 * il0 + bv;
        o1 += xch[1 * 128 + d] + av1 * il1 + bv;
        o2 += xch[2 * 128 + d] + av2 * il2 + bv;
        o3 += xch[3 * 128 + d] + av3 * il3 + bv;
        out[(i0 + 0) * DIM + d] = o0;
        out[(i0 + 1) * DIM + d] = o1;
        out[(i0 + 2) * DIM + d] = o2;
        out[(i0 + 3) * DIM + d] = o3;
    }
}

// ---------------------------------------------------------------------------
extern "C" void kernel_launch(void* const* d_in, const int* in_sizes, int n_in,
                              void* d_out, int out_size)
{
    const float* x    = (const float*)d_in[0];
    const float* W_Q  = (const float*)d_in[1];
    const float* b_Q  = (const float*)d_in[2];
    const float* W_K  = (const float*)d_in[3];
    const float* b_K  = (const float*)d_in[4];
    const float* W_V  = (const float*)d_in[5];
    const float* b_V  = (const float*)d_in[6];
    const float* W_Ev = (const float*)d_in[7];
    const float* b_Ev = (const float*)d_in[8];
    const float* W_A  = (const float*)d_in[9];
    // d_in[10] = b_A: cancels in softmax; sum(alpha)=1 handles b_Ev; unused.
    float* out = (float*)d_out;

    const int smem2 = 18064 * (int)sizeof(float);  // 72256 B -> 2 CTAs/SM
    cudaFuncSetAttribute(attn_kernel, cudaFuncAttributeMaxDynamicSharedMemorySize, smem2);

    qkv_kernel<<<NTOK / 8, 384>>>(x, W_Q, b_Q, W_K, b_K, W_V, b_V);
    attn_kernel<<<NTOK / TI, NT, smem2>>>(W_A, W_Ev, b_Ev, out);
}